// round 11
// baseline (speedup 1.0000x reference)
#include <cuda_runtime.h>

// Fused 5-point replicate-pad stencil + cubic Horner polynomial.
// R11: R10 (best, 80.4us) with the lane-0/31 horizontal-edge fix-up loads
// hoisted into the front load batch (before the shuffles), so every memory
// request issues back-to-back at the top of the thread. One CTA = one full
// row-quad (block=512); consecutive CTAs are vertically adjacent quads so
// halo-row re-reads hit L2 from the scheduling neighbor.

#define H_DIM 2048
#define W_DIM 2048
#define W4    (W_DIM / 4)   // 512
#define HQ    (H_DIM / 4)   // 512 row-quads per plane

__global__ void __launch_bounds__(512) stencil_poly_4row(
    const float* __restrict__ x,
    const float* __restrict__ a,
    const float* __restrict__ w,
    float* __restrict__ out,
    int nplanes)
{
    int rq = blockIdx.x & (HQ - 1);        // row-quad within plane
    int p  = blockIdx.x >> 9;              // / HQ (512)

    int c4 = threadIdx.x;                  // 0..511 (full row)
    int rbase = rq << 2;

    int plane_off = p * (H_DIM * W_DIM);   // < 2^31
    const float* plane = x + plane_off;

    int rtop = (rbase > 0) ? rbase - 1 : 0;
    int rbot = (rbase + 4 < H_DIM) ? rbase + 4 : H_DIM - 1;

    // ---- front load batch: 6 vector row loads + predicated edge scalars ----
    float4 v[6];
    v[0] = __ldg((const float4*)(plane + rtop        * W_DIM) + c4);
    v[1] = __ldg((const float4*)(plane + (rbase    ) * W_DIM) + c4);
    v[2] = __ldg((const float4*)(plane + (rbase + 1) * W_DIM) + c4);
    v[3] = __ldg((const float4*)(plane + (rbase + 2) * W_DIM) + c4);
    v[4] = __ldg((const float4*)(plane + (rbase + 3) * W_DIM) + c4);
    v[5] = __ldg((const float4*)(plane + rbot        * W_DIM) + c4);

    int lane = threadIdx.x & 31;
    int c = c4 << 2;
    bool edge_l = (lane == 0)  && (c != 0);
    bool edge_r = (lane == 31) && (c + 4 != W_DIM);

    float el[4], er[4];
    #pragma unroll
    for (int i = 0; i < 4; i++) {
        const float* row = plane + (rbase + i) * W_DIM;
        el[i] = edge_l ? __ldg(row + c - 1) : 0.0f;
        er[i] = edge_r ? __ldg(row + c + 4) : 0.0f;
    }

    // ---- shuffles + edge select (pure compute from here) ----
    float lh[4], rh[4];
    #pragma unroll
    for (int i = 0; i < 4; i++) {
        lh[i] = __shfl_up_sync  (0xFFFFFFFFu, v[i + 1].w, 1);
        rh[i] = __shfl_down_sync(0xFFFFFFFFu, v[i + 1].x, 1);
        if (lane == 0)  lh[i] = (c == 0)         ? v[i + 1].x : el[i];
        if (lane == 31) rh[i] = (c + 4 == W_DIM) ? v[i + 1].w : er[i];
    }

    float a0 = __ldg(a + 0), a1 = __ldg(a + 1), a2 = __ldg(a + 2);
    float w0 = __ldg(w + 0), w1 = __ldg(w + 1), w2 = __ldg(w + 2), w3 = __ldg(w + 3);

    float* oplane = out + plane_off;

    #pragma unroll
    for (int i = 0; i < 4; i++) {
        float4 cv = v[i + 1];
        float4 up = v[i];
        float4 dn = v[i + 2];
        float4 o;

        float xv = cv.x;
        o.x = a0*xv + a1*(lh[i] + cv.y) + a2*(up.x + dn.x)
            + fmaf(fmaf(fmaf(w3, xv, w2), xv, w1), xv, w0);
        xv = cv.y;
        o.y = a0*xv + a1*(cv.x + cv.z) + a2*(up.y + dn.y)
            + fmaf(fmaf(fmaf(w3, xv, w2), xv, w1), xv, w0);
        xv = cv.z;
        o.z = a0*xv + a1*(cv.y + cv.w) + a2*(up.z + dn.z)
            + fmaf(fmaf(fmaf(w3, xv, w2), xv, w1), xv, w0);
        xv = cv.w;
        o.w = a0*xv + a1*(cv.z + rh[i]) + a2*(up.w + dn.w)
            + fmaf(fmaf(fmaf(w3, xv, w2), xv, w1), xv, w0);

        __stcs((float4*)(oplane + (rbase + i) * W_DIM) + c4, o);
    }
}

extern "C" void kernel_launch(void* const* d_in, const int* in_sizes, int n_in,
                              void* d_out, int out_size)
{
    const float* x = (const float*)d_in[0];
    const float* a = (const float*)d_in[1];
    const float* w = (const float*)d_in[2];
    float* out = (float*)d_out;

    int n = in_sizes[0];
    int nplanes = n / (H_DIM * W_DIM);  // B*C = 16

    int blocks = nplanes * HQ;          // 16 * 512 = 8192 CTAs
    stencil_poly_4row<<<blocks, 512>>>(x, a, w, out, nplanes);
}

// round 12
// speedup vs baseline: 1.0063x; 1.0063x over previous
#include <cuda_runtime.h>

// Fused 5-point replicate-pad stencil + cubic Horner polynomial.
// FINAL (= R10, session best 80.4us harness): one CTA = one full row-quad
// (block=512, 512 float4 wide x 4 rows). 6 front-batched LDG.128 produce
// 4 float4 outputs (1.5 row-loads/output); horizontal halo via warp shuffle
// (warps are row-aligned); streaming stores (__stcs). Consecutive CTAs are
// vertically adjacent quads so halo-row re-reads hit L2 from the scheduling
// neighbor.
//
// Evidence this is the wall: across RPT={1,2,4,8}, persistent-CTA, 3D-grid,
// block={256,512}, and edge-load hoisting, achieved HBM stayed 6.1-6.3 TB/s
// with DRAM traffic at the 537MB minimum and all compute pipes <45%.

#define H_DIM 2048
#define W_DIM 2048
#define W4    (W_DIM / 4)   // 512
#define HQ    (H_DIM / 4)   // 512 row-quads per plane

__global__ void __launch_bounds__(512) stencil_poly_4row(
    const float* __restrict__ x,
    const float* __restrict__ a,
    const float* __restrict__ w,
    float* __restrict__ out,
    int nplanes)
{
    // blockIdx.x = quad index; quads sweep rows fastest, then planes.
    int rq = blockIdx.x & (HQ - 1);        // row-quad within plane
    int p  = blockIdx.x >> 9;              // / HQ (512)

    int c4 = threadIdx.x;                  // 0..511 (full row)
    int rbase = rq << 2;

    int plane_off = p * (H_DIM * W_DIM);   // < 2^31
    const float* plane = x + plane_off;

    int rtop = (rbase > 0) ? rbase - 1 : 0;
    int rbot = (rbase + 4 < H_DIM) ? rbase + 4 : H_DIM - 1;

    // 6 front-batched row loads: rbase-1 .. rbase+4, clamped.
    float4 v[6];
    v[0] = __ldg((const float4*)(plane + rtop        * W_DIM) + c4);
    v[1] = __ldg((const float4*)(plane + (rbase    ) * W_DIM) + c4);
    v[2] = __ldg((const float4*)(plane + (rbase + 1) * W_DIM) + c4);
    v[3] = __ldg((const float4*)(plane + (rbase + 2) * W_DIM) + c4);
    v[4] = __ldg((const float4*)(plane + (rbase + 3) * W_DIM) + c4);
    v[5] = __ldg((const float4*)(plane + rbot        * W_DIM) + c4);

    // horizontal halo via shuffle (warps row-aligned: 512 % 32 == 0).
    int lane = threadIdx.x & 31;
    int c = c4 << 2;
    float lh[4], rh[4];
    #pragma unroll
    for (int i = 0; i < 4; i++) {
        lh[i] = __shfl_up_sync  (0xFFFFFFFFu, v[i + 1].w, 1);
        rh[i] = __shfl_down_sync(0xFFFFFFFFu, v[i + 1].x, 1);
    }
    if (lane == 0) {
        #pragma unroll
        for (int i = 0; i < 4; i++) {
            const float* row = plane + (rbase + i) * W_DIM;
            lh[i] = (c == 0) ? v[i + 1].x : __ldg(row + c - 1);
        }
    }
    if (lane == 31) {
        #pragma unroll
        for (int i = 0; i < 4; i++) {
            const float* row = plane + (rbase + i) * W_DIM;
            rh[i] = (c + 4 == W_DIM) ? v[i + 1].w : __ldg(row + c + 4);
        }
    }

    float a0 = __ldg(a + 0), a1 = __ldg(a + 1), a2 = __ldg(a + 2);
    float w0 = __ldg(w + 0), w1 = __ldg(w + 1), w2 = __ldg(w + 2), w3 = __ldg(w + 3);

    float* oplane = out + plane_off;

    #pragma unroll
    for (int i = 0; i < 4; i++) {
        float4 cv = v[i + 1];
        float4 up = v[i];
        float4 dn = v[i + 2];
        float4 o;

        float xv = cv.x;
        o.x = a0*xv + a1*(lh[i] + cv.y) + a2*(up.x + dn.x)
            + fmaf(fmaf(fmaf(w3, xv, w2), xv, w1), xv, w0);
        xv = cv.y;
        o.y = a0*xv + a1*(cv.x + cv.z) + a2*(up.y + dn.y)
            + fmaf(fmaf(fmaf(w3, xv, w2), xv, w1), xv, w0);
        xv = cv.z;
        o.z = a0*xv + a1*(cv.y + cv.w) + a2*(up.z + dn.z)
            + fmaf(fmaf(fmaf(w3, xv, w2), xv, w1), xv, w0);
        xv = cv.w;
        o.w = a0*xv + a1*(cv.z + rh[i]) + a2*(up.w + dn.w)
            + fmaf(fmaf(fmaf(w3, xv, w2), xv, w1), xv, w0);

        __stcs((float4*)(oplane + (rbase + i) * W_DIM) + c4, o);
    }
}

extern "C" void kernel_launch(void* const* d_in, const int* in_sizes, int n_in,
                              void* d_out, int out_size)
{
    const float* x = (const float*)d_in[0];
    const float* a = (const float*)d_in[1];
    const float* w = (const float*)d_in[2];
    float* out = (float*)d_out;

    int n = in_sizes[0];
    int nplanes = n / (H_DIM * W_DIM);  // B*C = 16

    int blocks = nplanes * HQ;          // 16 * 512 = 8192 CTAs
    stencil_poly_4row<<<blocks, 512>>>(x, a, w, out, nplanes);
}

// round 13
// speedup vs baseline: 1.0083x; 1.0020x over previous
#include <cuda_runtime.h>

// Fused 5-point replicate-pad stencil + cubic Horner polynomial.
// R13: R10 (session best) with ONE variable changed — plain write-back
// stores instead of __stcs streaming stores. A/B test of store cache
// policy: evict-first may force eager writebacks and reduce DRAM burst
// coalescing; L2 has idle capacity (43% busy) to buffer dirty lines.
// Everything else byte-identical to R10.

#define H_DIM 2048
#define W_DIM 2048
#define W4    (W_DIM / 4)   // 512
#define HQ    (H_DIM / 4)   // 512 row-quads per plane

__global__ void __launch_bounds__(512) stencil_poly_4row(
    const float* __restrict__ x,
    const float* __restrict__ a,
    const float* __restrict__ w,
    float* __restrict__ out,
    int nplanes)
{
    // blockIdx.x = quad index; quads sweep rows fastest, then planes.
    int rq = blockIdx.x & (HQ - 1);        // row-quad within plane
    int p  = blockIdx.x >> 9;              // / HQ (512)

    int c4 = threadIdx.x;                  // 0..511 (full row)
    int rbase = rq << 2;

    int plane_off = p * (H_DIM * W_DIM);   // < 2^31
    const float* plane = x + plane_off;

    int rtop = (rbase > 0) ? rbase - 1 : 0;
    int rbot = (rbase + 4 < H_DIM) ? rbase + 4 : H_DIM - 1;

    // 6 front-batched row loads: rbase-1 .. rbase+4, clamped.
    float4 v[6];
    v[0] = __ldg((const float4*)(plane + rtop        * W_DIM) + c4);
    v[1] = __ldg((const float4*)(plane + (rbase    ) * W_DIM) + c4);
    v[2] = __ldg((const float4*)(plane + (rbase + 1) * W_DIM) + c4);
    v[3] = __ldg((const float4*)(plane + (rbase + 2) * W_DIM) + c4);
    v[4] = __ldg((const float4*)(plane + (rbase + 3) * W_DIM) + c4);
    v[5] = __ldg((const float4*)(plane + rbot        * W_DIM) + c4);

    // horizontal halo via shuffle (warps row-aligned: 512 % 32 == 0).
    int lane = threadIdx.x & 31;
    int c = c4 << 2;
    float lh[4], rh[4];
    #pragma unroll
    for (int i = 0; i < 4; i++) {
        lh[i] = __shfl_up_sync  (0xFFFFFFFFu, v[i + 1].w, 1);
        rh[i] = __shfl_down_sync(0xFFFFFFFFu, v[i + 1].x, 1);
    }
    if (lane == 0) {
        #pragma unroll
        for (int i = 0; i < 4; i++) {
            const float* row = plane + (rbase + i) * W_DIM;
            lh[i] = (c == 0) ? v[i + 1].x : __ldg(row + c - 1);
        }
    }
    if (lane == 31) {
        #pragma unroll
        for (int i = 0; i < 4; i++) {
            const float* row = plane + (rbase + i) * W_DIM;
            rh[i] = (c + 4 == W_DIM) ? v[i + 1].w : __ldg(row + c + 4);
        }
    }

    float a0 = __ldg(a + 0), a1 = __ldg(a + 1), a2 = __ldg(a + 2);
    float w0 = __ldg(w + 0), w1 = __ldg(w + 1), w2 = __ldg(w + 2), w3 = __ldg(w + 3);

    float* oplane = out + plane_off;

    #pragma unroll
    for (int i = 0; i < 4; i++) {
        float4 cv = v[i + 1];
        float4 up = v[i];
        float4 dn = v[i + 2];
        float4 o;

        float xv = cv.x;
        o.x = a0*xv + a1*(lh[i] + cv.y) + a2*(up.x + dn.x)
            + fmaf(fmaf(fmaf(w3, xv, w2), xv, w1), xv, w0);
        xv = cv.y;
        o.y = a0*xv + a1*(cv.x + cv.z) + a2*(up.y + dn.y)
            + fmaf(fmaf(fmaf(w3, xv, w2), xv, w1), xv, w0);
        xv = cv.z;
        o.z = a0*xv + a1*(cv.y + cv.w) + a2*(up.z + dn.z)
            + fmaf(fmaf(fmaf(w3, xv, w2), xv, w1), xv, w0);
        xv = cv.w;
        o.w = a0*xv + a1*(cv.z + rh[i]) + a2*(up.w + dn.w)
            + fmaf(fmaf(fmaf(w3, xv, w2), xv, w1), xv, w0);

        // plain write-back store (A/B vs __stcs in R10)
        ((float4*)(oplane + (rbase + i) * W_DIM))[c4] = o;
    }
}

extern "C" void kernel_launch(void* const* d_in, const int* in_sizes, int n_in,
                              void* d_out, int out_size)
{
    const float* x = (const float*)d_in[0];
    const float* a = (const float*)d_in[1];
    const float* w = (const float*)d_in[2];
    float* out = (float*)d_out;

    int n = in_sizes[0];
    int nplanes = n / (H_DIM * W_DIM);  // B*C = 16

    int blocks = nplanes * HQ;          // 16 * 512 = 8192 CTAs
    stencil_poly_4row<<<blocks, 512>>>(x, a, w, out, nplanes);
}

// round 14
// speedup vs baseline: 1.0203x; 1.0119x over previous
#include <cuda_runtime.h>

// Fused 5-point replicate-pad stencil + cubic Horner polynomial.
// FINAL (= R10, session best 80.4us harness / 76.8us ncu):
//   - one CTA = one full row-quad (block=512: 512 float4 wide x 4 rows)
//   - 6 front-batched LDG.128 produce 4 float4 outputs (1.5 row-loads/output)
//   - horizontal halo via warp shuffle (warps are row-aligned: 512%32==0)
//   - streaming stores (__stcs); A/B vs plain stores was neutral
//   - consecutive CTAs are vertically adjacent quads -> halo-row re-reads
//     hit L2 from the scheduling neighbor
//
// Saturation evidence: across RPT={1,2,4,8}, persistent-CTA, 3D-grid,
// block={256,512}, edge-load hoisting, and store-policy A/B, achieved HBM
// stayed pinned at 6.1-6.3 TB/s with DRAM traffic at the 537MB minimum and
// all compute pipes <45%. This kernel runs at the mixed r/w memory wall.

#define H_DIM 2048
#define W_DIM 2048
#define W4    (W_DIM / 4)   // 512
#define HQ    (H_DIM / 4)   // 512 row-quads per plane

__global__ void __launch_bounds__(512) stencil_poly_4row(
    const float* __restrict__ x,
    const float* __restrict__ a,
    const float* __restrict__ w,
    float* __restrict__ out,
    int nplanes)
{
    // blockIdx.x = quad index; quads sweep rows fastest, then planes.
    int rq = blockIdx.x & (HQ - 1);        // row-quad within plane
    int p  = blockIdx.x >> 9;              // / HQ (512)

    int c4 = threadIdx.x;                  // 0..511 (full row)
    int rbase = rq << 2;

    int plane_off = p * (H_DIM * W_DIM);   // < 2^31
    const float* plane = x + plane_off;

    int rtop = (rbase > 0) ? rbase - 1 : 0;
    int rbot = (rbase + 4 < H_DIM) ? rbase + 4 : H_DIM - 1;

    // 6 front-batched row loads: rbase-1 .. rbase+4, clamped.
    float4 v[6];
    v[0] = __ldg((const float4*)(plane + rtop        * W_DIM) + c4);
    v[1] = __ldg((const float4*)(plane + (rbase    ) * W_DIM) + c4);
    v[2] = __ldg((const float4*)(plane + (rbase + 1) * W_DIM) + c4);
    v[3] = __ldg((const float4*)(plane + (rbase + 2) * W_DIM) + c4);
    v[4] = __ldg((const float4*)(plane + (rbase + 3) * W_DIM) + c4);
    v[5] = __ldg((const float4*)(plane + rbot        * W_DIM) + c4);

    // horizontal halo via shuffle (warps row-aligned: 512 % 32 == 0).
    int lane = threadIdx.x & 31;
    int c = c4 << 2;
    float lh[4], rh[4];
    #pragma unroll
    for (int i = 0; i < 4; i++) {
        lh[i] = __shfl_up_sync  (0xFFFFFFFFu, v[i + 1].w, 1);
        rh[i] = __shfl_down_sync(0xFFFFFFFFu, v[i + 1].x, 1);
    }
    if (lane == 0) {
        #pragma unroll
        for (int i = 0; i < 4; i++) {
            const float* row = plane + (rbase + i) * W_DIM;
            lh[i] = (c == 0) ? v[i + 1].x : __ldg(row + c - 1);
        }
    }
    if (lane == 31) {
        #pragma unroll
        for (int i = 0; i < 4; i++) {
            const float* row = plane + (rbase + i) * W_DIM;
            rh[i] = (c + 4 == W_DIM) ? v[i + 1].w : __ldg(row + c + 4);
        }
    }

    float a0 = __ldg(a + 0), a1 = __ldg(a + 1), a2 = __ldg(a + 2);
    float w0 = __ldg(w + 0), w1 = __ldg(w + 1), w2 = __ldg(w + 2), w3 = __ldg(w + 3);

    float* oplane = out + plane_off;

    #pragma unroll
    for (int i = 0; i < 4; i++) {
        float4 cv = v[i + 1];
        float4 up = v[i];
        float4 dn = v[i + 2];
        float4 o;

        float xv = cv.x;
        o.x = a0*xv + a1*(lh[i] + cv.y) + a2*(up.x + dn.x)
            + fmaf(fmaf(fmaf(w3, xv, w2), xv, w1), xv, w0);
        xv = cv.y;
        o.y = a0*xv + a1*(cv.x + cv.z) + a2*(up.y + dn.y)
            + fmaf(fmaf(fmaf(w3, xv, w2), xv, w1), xv, w0);
        xv = cv.z;
        o.z = a0*xv + a1*(cv.y + cv.w) + a2*(up.z + dn.z)
            + fmaf(fmaf(fmaf(w3, xv, w2), xv, w1), xv, w0);
        xv = cv.w;
        o.w = a0*xv + a1*(cv.z + rh[i]) + a2*(up.w + dn.w)
            + fmaf(fmaf(fmaf(w3, xv, w2), xv, w1), xv, w0);

        __stcs((float4*)(oplane + (rbase + i) * W_DIM) + c4, o);
    }
}

extern "C" void kernel_launch(void* const* d_in, const int* in_sizes, int n_in,
                              void* d_out, int out_size)
{
    const float* x = (const float*)d_in[0];
    const float* a = (const float*)d_in[1];
    const float* w = (const float*)d_in[2];
    float* out = (float*)d_out;

    int n = in_sizes[0];
    int nplanes = n / (H_DIM * W_DIM);  // B*C = 16

    int blocks = nplanes * HQ;          // 16 * 512 = 8192 CTAs
    stencil_poly_4row<<<blocks, 512>>>(x, a, w, out, nplanes);
}

// round 15
// speedup vs baseline: 1.0207x; 1.0004x over previous
#include <cuda_runtime.h>

// Fused 5-point replicate-pad stencil + cubic Horner polynomial.
// FINAL (= R10, confirmed twice at 80.4us harness / 76.7us ncu):
//   - one CTA = one full row-quad (block=512: 512 float4 wide x 4 rows)
//   - 6 front-batched LDG.128 produce 4 float4 outputs (1.5 row-loads/output)
//   - horizontal halo via warp shuffle (warps are row-aligned: 512%32==0)
//   - streaming stores (__stcs); A/B vs plain stores was neutral
//   - consecutive CTAs are vertically adjacent quads -> halo-row re-reads
//     hit L2 from the scheduling neighbor
//
// Saturation evidence (9 perturbation axes, R4-R13): RPT={1,2,4,8},
// block={256,512}, grid={1D,3D,persistent}, 32/64-bit indexing, halo via
// loads vs shuffle, edge-load placement, store policy — all pinned at
// 6.1-6.3 TB/s with DRAM traffic at the 537MB minimum and all compute
// pipes <45%. This kernel runs at the mixed r/w memory wall.

#define H_DIM 2048
#define W_DIM 2048
#define W4    (W_DIM / 4)   // 512
#define HQ    (H_DIM / 4)   // 512 row-quads per plane

__global__ void __launch_bounds__(512) stencil_poly_4row(
    const float* __restrict__ x,
    const float* __restrict__ a,
    const float* __restrict__ w,
    float* __restrict__ out,
    int nplanes)
{
    // blockIdx.x = quad index; quads sweep rows fastest, then planes.
    int rq = blockIdx.x & (HQ - 1);        // row-quad within plane
    int p  = blockIdx.x >> 9;              // / HQ (512)

    int c4 = threadIdx.x;                  // 0..511 (full row)
    int rbase = rq << 2;

    int plane_off = p * (H_DIM * W_DIM);   // < 2^31
    const float* plane = x + plane_off;

    int rtop = (rbase > 0) ? rbase - 1 : 0;
    int rbot = (rbase + 4 < H_DIM) ? rbase + 4 : H_DIM - 1;

    // 6 front-batched row loads: rbase-1 .. rbase+4, clamped.
    float4 v[6];
    v[0] = __ldg((const float4*)(plane + rtop        * W_DIM) + c4);
    v[1] = __ldg((const float4*)(plane + (rbase    ) * W_DIM) + c4);
    v[2] = __ldg((const float4*)(plane + (rbase + 1) * W_DIM) + c4);
    v[3] = __ldg((const float4*)(plane + (rbase + 2) * W_DIM) + c4);
    v[4] = __ldg((const float4*)(plane + (rbase + 3) * W_DIM) + c4);
    v[5] = __ldg((const float4*)(plane + rbot        * W_DIM) + c4);

    // horizontal halo via shuffle (warps row-aligned: 512 % 32 == 0).
    int lane = threadIdx.x & 31;
    int c = c4 << 2;
    float lh[4], rh[4];
    #pragma unroll
    for (int i = 0; i < 4; i++) {
        lh[i] = __shfl_up_sync  (0xFFFFFFFFu, v[i + 1].w, 1);
        rh[i] = __shfl_down_sync(0xFFFFFFFFu, v[i + 1].x, 1);
    }
    if (lane == 0) {
        #pragma unroll
        for (int i = 0; i < 4; i++) {
            const float* row = plane + (rbase + i) * W_DIM;
            lh[i] = (c == 0) ? v[i + 1].x : __ldg(row + c - 1);
        }
    }
    if (lane == 31) {
        #pragma unroll
        for (int i = 0; i < 4; i++) {
            const float* row = plane + (rbase + i) * W_DIM;
            rh[i] = (c + 4 == W_DIM) ? v[i + 1].w : __ldg(row + c + 4);
        }
    }

    float a0 = __ldg(a + 0), a1 = __ldg(a + 1), a2 = __ldg(a + 2);
    float w0 = __ldg(w + 0), w1 = __ldg(w + 1), w2 = __ldg(w + 2), w3 = __ldg(w + 3);

    float* oplane = out + plane_off;

    #pragma unroll
    for (int i = 0; i < 4; i++) {
        float4 cv = v[i + 1];
        float4 up = v[i];
        float4 dn = v[i + 2];
        float4 o;

        float xv = cv.x;
        o.x = a0*xv + a1*(lh[i] + cv.y) + a2*(up.x + dn.x)
            + fmaf(fmaf(fmaf(w3, xv, w2), xv, w1), xv, w0);
        xv = cv.y;
        o.y = a0*xv + a1*(cv.x + cv.z) + a2*(up.y + dn.y)
            + fmaf(fmaf(fmaf(w3, xv, w2), xv, w1), xv, w0);
        xv = cv.z;
        o.z = a0*xv + a1*(cv.y + cv.w) + a2*(up.z + dn.z)
            + fmaf(fmaf(fmaf(w3, xv, w2), xv, w1), xv, w0);
        xv = cv.w;
        o.w = a0*xv + a1*(cv.z + rh[i]) + a2*(up.w + dn.w)
            + fmaf(fmaf(fmaf(w3, xv, w2), xv, w1), xv, w0);

        __stcs((float4*)(oplane + (rbase + i) * W_DIM) + c4, o);
    }
}

extern "C" void kernel_launch(void* const* d_in, const int* in_sizes, int n_in,
                              void* d_out, int out_size)
{
    const float* x = (const float*)d_in[0];
    const float* a = (const float*)d_in[1];
    const float* w = (const float*)d_in[2];
    float* out = (float*)d_out;

    int n = in_sizes[0];
    int nplanes = n / (H_DIM * W_DIM);  // B*C = 16

    int blocks = nplanes * HQ;          // 16 * 512 = 8192 CTAs
    stencil_poly_4row<<<blocks, 512>>>(x, a, w, out, nplanes);
}